// round 9
// baseline (speedup 1.0000x reference)
#include <cuda_runtime.h>
#include <math.h>
#include <stdint.h>

#define B_   8
#define LQ_  2048
#define LK_  2048
#define HID_ 1024

// smem strides (floats): k-major tiles [row][k] stride 20; n-major [k][n] stride 136.
#define SK 20
#define SN 136

// tf32-rounded scratch copies (rna applied once; GEMMs then load raw bits)
__device__ unsigned g_Qt[(size_t)B_ * LQ_ * HID_];   // 64MB
__device__ unsigned g_Kt[(size_t)B_ * LK_ * HID_];   // 64MB
__device__ unsigned g_At[(size_t)B_ * LQ_ * LK_];    // 128MB

__device__ __forceinline__ unsigned f2tf(float x) {
    unsigned u;
    asm("cvt.rna.tf32.f32 %0, %1;" : "=r"(u) : "f"(x));
    return u;
}

__device__ __forceinline__ void mma_tf32(float* d, const unsigned* a, const unsigned* b) {
    asm volatile(
        "mma.sync.aligned.m16n8k8.row.col.f32.tf32.tf32.f32 "
        "{%0,%1,%2,%3}, {%4,%5,%6,%7}, {%8,%9}, {%0,%1,%2,%3};\n"
        : "+f"(d[0]), "+f"(d[1]), "+f"(d[2]), "+f"(d[3])
        : "r"(a[0]), "r"(a[1]), "r"(a[2]), "r"(a[3]),
          "r"(b[0]), "r"(b[1]));
}

__device__ __forceinline__ void cp_async16(uint32_t smem_addr, const void* gptr) {
    asm volatile("cp.async.cg.shared.global [%0], [%1], 16;"
                 :: "r"(smem_addr), "l"(gptr));
}
#define CP_COMMIT() asm volatile("cp.async.commit_group;" ::: "memory")
#define CP_WAIT0()  asm volatile("cp.async.wait_group 0;" ::: "memory")

// ---------------------------------------------------------------------------
// Kernel 0: elementwise rna-round to tf32 bits (vectorized)
// ---------------------------------------------------------------------------
__global__ __launch_bounds__(256)
void k0_round(const float* __restrict__ src, unsigned* __restrict__ dst, int n4)
{
    const int i = blockIdx.x * 256 + threadIdx.x;
    if (i < n4) {
        float4 v = ((const float4*)src)[i];
        ((uint4*)dst)[i] = make_uint4(f2tf(v.x), f2tf(v.y), f2tf(v.z), f2tf(v.w));
    }
}

// ---------------------------------------------------------------------------
// Kernel 1: P = exp( (Qt.Kt^T / 32) * mask )  (unnormalized; k2 normalizes)
// CTA 128x128, BK=16, 128 threads = 4 warps (2Mx2N), warp tile 64x64.
// cp.async staging of pre-rounded tf32 bits. 2 CTAs/SM.
// ---------------------------------------------------------------------------
__global__ __launch_bounds__(128, 2)
void k1_qk_exp(const unsigned* __restrict__ Q, const unsigned* __restrict__ Kf,
               const float* __restrict__ mask, float* __restrict__ P)
{
    extern __shared__ unsigned sm[];
    unsigned* sA[2] = { sm,              sm + 128 * SK };
    unsigned* sB[2] = { sm + 2 * 128 * SK, sm + 3 * 128 * SK };

    const int b  = blockIdx.z;
    const int m0 = blockIdx.y * 128;
    const int n0 = blockIdx.x * 128;

    const unsigned* Qb = Q  + (size_t)b * LQ_ * HID_;
    const unsigned* Kb = Kf + (size_t)b * LK_ * HID_;

    const int tid  = threadIdx.x;
    const int wid  = tid >> 5;
    const int lane = tid & 31;
    const int qid  = lane >> 2;
    const int rid  = lane & 3;
    const int wm   = (wid & 1) * 64;
    const int wn   = (wid >> 1) * 64;

    const int lrow = tid >> 2;          // 0..31
    const int lkq  = (tid & 3) << 2;    // 0,4,8,12

    uint32_t sAa[2], sBa[2];
#pragma unroll
    for (int u = 0; u < 2; u++) {
        sAa[u] = (uint32_t)__cvta_generic_to_shared(sA[u]);
        sBa[u] = (uint32_t)__cvta_generic_to_shared(sB[u]);
    }

    float acc[4][8][4];
#pragma unroll
    for (int i = 0; i < 4; i++)
#pragma unroll
        for (int j = 0; j < 8; j++)
#pragma unroll
            for (int c = 0; c < 4; c++) acc[i][j][c] = 0.0f;

    auto fill = [&](int stage, int buf) {
        const int kk = stage * 16;
#pragma unroll
        for (int j = 0; j < 4; j++) {
            const int row = lrow + j * 32;
            cp_async16(sAa[buf] + (row * SK + lkq) * 4,
                       Qb + (size_t)(m0 + row) * HID_ + kk + lkq);
            cp_async16(sBa[buf] + (row * SK + lkq) * 4,
                       Kb + (size_t)(n0 + row) * HID_ + kk + lkq);
        }
    };

    fill(0, 0);
    CP_COMMIT();

    const int NIT = HID_ / 16;
    for (int it = 0; it < NIT; it++) {
        CP_WAIT0();
        __syncthreads();
        const int cur = it & 1;
        if (it + 1 < NIT) {
            fill(it + 1, cur ^ 1);
            CP_COMMIT();
        }
        const unsigned* cA = sA[cur];
        const unsigned* cB = sB[cur];

#pragma unroll
        for (int ks = 0; ks < 16; ks += 8) {
            unsigned af[4][4];
#pragma unroll
            for (int mt = 0; mt < 4; mt++) {
                const int r = wm + mt * 16 + qid;
                af[mt][0] = cA[r * SK + ks + rid];
                af[mt][1] = cA[(r + 8) * SK + ks + rid];
                af[mt][2] = cA[r * SK + ks + 4 + rid];
                af[mt][3] = cA[(r + 8) * SK + ks + 4 + rid];
            }
            unsigned bf[8][2];
#pragma unroll
            for (int nt = 0; nt < 8; nt++) {
                const int c = wn + nt * 8 + qid;
                bf[nt][0] = cB[c * SK + ks + rid];
                bf[nt][1] = cB[c * SK + ks + 4 + rid];
            }
#pragma unroll
            for (int mt = 0; mt < 4; mt++)
#pragma unroll
                for (int nt = 0; nt < 8; nt++)
                    mma_tf32(acc[mt][nt], af[mt], bf[nt]);
        }
    }

    const float s = 0.03125f;
#pragma unroll
    for (int mt = 0; mt < 4; mt++) {
#pragma unroll
        for (int nt = 0; nt < 8; nt++) {
            const int r = m0 + wm + mt * 16 + qid;
            const int c = n0 + wn + nt * 8 + 2 * rid;
            const size_t i0 = ((size_t)b * LQ_ + r) * LK_ + c;
            const size_t i1 = ((size_t)b * LQ_ + r + 8) * LK_ + c;
            float2 ma = *(const float2*)(mask + i0);
            float2 mb = *(const float2*)(mask + i1);
            float2 o0, o1;
            o0.x = __expf(acc[mt][nt][0] * s * ma.x);
            o0.y = __expf(acc[mt][nt][1] * s * ma.y);
            o1.x = __expf(acc[mt][nt][2] * s * mb.x);
            o1.y = __expf(acc[mt][nt][3] * s * mb.y);
            *(float2*)(P + i0) = o0;
            *(float2*)(P + i1) = o1;
        }
    }
}

// ---------------------------------------------------------------------------
// Kernel 2: per-row normalization; also emit rna-rounded tf32 copy to g_At
// ---------------------------------------------------------------------------
__global__ __launch_bounds__(256)
void k2_norm(float* __restrict__ P, unsigned* __restrict__ Pt)
{
    __shared__ float red[256];
    float*    prow = P  + (size_t)blockIdx.x * LK_;
    unsigned* trow = Pt + (size_t)blockIdx.x * LK_;
    const int tid = threadIdx.x;

    float4 v0 = ((const float4*)prow)[tid];
    float4 v1 = ((const float4*)prow)[tid + 256];
    float s = v0.x + v0.y + v0.z + v0.w + v1.x + v1.y + v1.z + v1.w;
    red[tid] = s;
    __syncthreads();
#pragma unroll
    for (int off = 128; off > 0; off >>= 1) {
        if (tid < off) red[tid] += red[tid + off];
        __syncthreads();
    }
    const float inv = 1.0f / red[0];
    v0.x *= inv; v0.y *= inv; v0.z *= inv; v0.w *= inv;
    v1.x *= inv; v1.y *= inv; v1.z *= inv; v1.w *= inv;
    ((float4*)prow)[tid]       = v0;
    ((float4*)prow)[tid + 256] = v1;
    ((uint4*)trow)[tid] =
        make_uint4(f2tf(v0.x), f2tf(v0.y), f2tf(v0.z), f2tf(v0.w));
    ((uint4*)trow)[tid + 256] =
        make_uint4(f2tf(v1.x), f2tf(v1.y), f2tf(v1.z), f2tf(v1.w));
}

// ---------------------------------------------------------------------------
// Kernel 3: context = attn_t . Kt
// A [row][k] stride SK; B [k][n] stride SN. cp.async staging of tf32 bits.
// ---------------------------------------------------------------------------
__global__ __launch_bounds__(128, 2)
void k3_av(const unsigned* __restrict__ A, const unsigned* __restrict__ Kf,
           float* __restrict__ C)
{
    extern __shared__ unsigned sm[];
    unsigned* sA[2] = { sm,              sm + 128 * SK };
    unsigned* sB[2] = { sm + 2 * 128 * SK, sm + 2 * 128 * SK + 16 * SN };

    const int b  = blockIdx.z;
    const int m0 = blockIdx.y * 128;
    const int n0 = blockIdx.x * 128;

    const unsigned* Ab = A  + (size_t)b * LQ_ * LK_;
    const unsigned* Kb = Kf + (size_t)b * LK_ * HID_;

    const int tid  = threadIdx.x;
    const int wid  = tid >> 5;
    const int lane = tid & 31;
    const int qid  = lane >> 2;
    const int rid  = lane & 3;
    const int wm   = (wid & 1) * 64;
    const int wn   = (wid >> 1) * 64;

    const int lrow = tid >> 2;
    const int lkq  = (tid & 3) << 2;
    const int lkr  = tid >> 5;          // 0..3
    const int lnc  = (tid & 31) << 2;   // 0..124

    uint32_t sAa[2], sBa[2];
#pragma unroll
    for (int u = 0; u < 2; u++) {
        sAa[u] = (uint32_t)__cvta_generic_to_shared(sA[u]);
        sBa[u] = (uint32_t)__cvta_generic_to_shared(sB[u]);
    }

    float acc[4][8][4];
#pragma unroll
    for (int i = 0; i < 4; i++)
#pragma unroll
        for (int j = 0; j < 8; j++)
#pragma unroll
            for (int c = 0; c < 4; c++) acc[i][j][c] = 0.0f;

    auto fill = [&](int stage, int buf) {
        const int kk = stage * 16;
#pragma unroll
        for (int j = 0; j < 4; j++) {
            const int row = lrow + j * 32;
            cp_async16(sAa[buf] + (row * SK + lkq) * 4,
                       Ab + (size_t)(m0 + row) * LK_ + kk + lkq);
            const int kr = lkr + j * 4;
            cp_async16(sBa[buf] + (kr * SN + lnc) * 4,
                       Kb + (size_t)(kk + kr) * HID_ + n0 + lnc);
        }
    };

    fill(0, 0);
    CP_COMMIT();

    const int NIT = LK_ / 16;
    for (int it = 0; it < NIT; it++) {
        CP_WAIT0();
        __syncthreads();
        const int cur = it & 1;
        if (it + 1 < NIT) {
            fill(it + 1, cur ^ 1);
            CP_COMMIT();
        }
        const unsigned* cA = sA[cur];
        const unsigned* cB = sB[cur];

#pragma unroll
        for (int ks = 0; ks < 16; ks += 8) {
            unsigned af[4][4];
#pragma unroll
            for (int mt = 0; mt < 4; mt++) {
                const int r = wm + mt * 16 + qid;
                af[mt][0] = cA[r * SK + ks + rid];
                af[mt][1] = cA[(r + 8) * SK + ks + rid];
                af[mt][2] = cA[r * SK + ks + 4 + rid];
                af[mt][3] = cA[(r + 8) * SK + ks + 4 + rid];
            }
            unsigned bf[8][2];
#pragma unroll
            for (int nt = 0; nt < 8; nt++) {
                const int c = wn + nt * 8 + qid;
                bf[nt][0] = cB[(ks + rid) * SN + c];
                bf[nt][1] = cB[(ks + 4 + rid) * SN + c];
            }
#pragma unroll
            for (int mt = 0; mt < 4; mt++)
#pragma unroll
                for (int nt = 0; nt < 8; nt++)
                    mma_tf32(acc[mt][nt], af[mt], bf[nt]);
        }
    }

#pragma unroll
    for (int mt = 0; mt < 4; mt++) {
#pragma unroll
        for (int nt = 0; nt < 8; nt++) {
            const int r = m0 + wm + mt * 16 + qid;
            const int c = n0 + wn + nt * 8 + 2 * rid;
            const size_t i0 = ((size_t)b * LQ_ + r) * HID_ + c;
            const size_t i1 = ((size_t)b * LQ_ + r + 8) * HID_ + c;
            *(float2*)(C + i0) = make_float2(acc[mt][nt][0], acc[mt][nt][1]);
            *(float2*)(C + i1) = make_float2(acc[mt][nt][2], acc[mt][nt][3]);
        }
    }
}

// ---------------------------------------------------------------------------
extern "C" void kernel_launch(void* const* d_in, const int* in_sizes, int n_in,
                              void* d_out, int out_size)
{
    const float* Q    = (const float*)d_in[0];
    const float* Kf   = (const float*)d_in[1];
    const float* mask = (const float*)d_in[2];

    float* ctx  = (float*)d_out;                      // [B, LQ, HID]
    float* attn = ctx + (size_t)B_ * LQ_ * HID_;      // [B, LQ, LK]

    void *qt = 0, *kt = 0, *at = 0;
    cudaGetSymbolAddress(&qt, g_Qt);
    cudaGetSymbolAddress(&kt, g_Kt);
    cudaGetSymbolAddress(&at, g_At);

    const int smem1 = (4 * 128 * SK) * 4;                 // 40960 B
    const int smem3 = (2 * 128 * SK + 2 * 16 * SN) * 4;   // 37888 B

    static bool attr_set = false;
    if (!attr_set) {
        cudaFuncSetAttribute(k1_qk_exp, cudaFuncAttributeMaxDynamicSharedMemorySize, smem1);
        cudaFuncSetAttribute(k3_av,     cudaFuncAttributeMaxDynamicSharedMemorySize, smem3);
        attr_set = true;
    }

    // k0: pre-round Q and K to tf32 bits
    const int n4 = (B_ * LQ_ * HID_) / 4;                 // 4.19M float4s
    k0_round<<<(n4 + 255) / 256, 256>>>(Q,  (unsigned*)qt, n4);
    k0_round<<<(n4 + 255) / 256, 256>>>(Kf, (unsigned*)kt, n4);

    dim3 g1(LK_ / 128, LQ_ / 128, B_);
    k1_qk_exp<<<g1, 128, smem1>>>((const unsigned*)qt, (const unsigned*)kt, mask, attn);

    k2_norm<<<B_ * LQ_, 256>>>(attn, (unsigned*)at);

    dim3 g3(HID_ / 128, LQ_ / 128, B_);
    k3_av<<<g3, 128, smem3>>>((const unsigned*)at, (const unsigned*)kt, ctx);
}

// round 10
// speedup vs baseline: 1.0544x; 1.0544x over previous
#include <cuda_runtime.h>
#include <math.h>
#include <stdint.h>

#define B_   8
#define LQ_  2048
#define LK_  2048
#define HID_ 1024

// smem strides (floats): k-major tiles [row][k] stride 20; n-major [k][n] stride 136.
#define SK 20
#define SN 136

// tf32-rounded scratch copies (rna applied once; GEMMs then load raw bits)
__device__ unsigned g_Qt[(size_t)B_ * LQ_ * HID_];   // 64MB
__device__ unsigned g_Kt[(size_t)B_ * LK_ * HID_];   // 64MB
__device__ unsigned g_At[(size_t)B_ * LQ_ * LK_];    // 128MB

__device__ __forceinline__ unsigned f2tf(float x) {
    unsigned u;
    asm("cvt.rna.tf32.f32 %0, %1;" : "=r"(u) : "f"(x));
    return u;
}

__device__ __forceinline__ void mma_tf32(float* d, const unsigned* a, const unsigned* b) {
    asm volatile(
        "mma.sync.aligned.m16n8k8.row.col.f32.tf32.tf32.f32 "
        "{%0,%1,%2,%3}, {%4,%5,%6,%7}, {%8,%9}, {%0,%1,%2,%3};\n"
        : "+f"(d[0]), "+f"(d[1]), "+f"(d[2]), "+f"(d[3])
        : "r"(a[0]), "r"(a[1]), "r"(a[2]), "r"(a[3]),
          "r"(b[0]), "r"(b[1]));
}

__device__ __forceinline__ void cp_async16(uint32_t smem_addr, const void* gptr) {
    asm volatile("cp.async.cg.shared.global [%0], [%1], 16;"
                 :: "r"(smem_addr), "l"(gptr));
}
#define CP_COMMIT() asm volatile("cp.async.commit_group;" ::: "memory")
#define CP_WAIT1()  asm volatile("cp.async.wait_group 1;" ::: "memory")

// ---------------------------------------------------------------------------
// Kernel 0: elementwise rna-round to tf32 bits (Q and K in one launch)
// ---------------------------------------------------------------------------
__global__ __launch_bounds__(256)
void k0_round(const float* __restrict__ q, const float* __restrict__ k,
              unsigned* __restrict__ qt, unsigned* __restrict__ kt, int n4)
{
    const int i = blockIdx.x * 256 + threadIdx.x;
    if (i < n4) {
        float4 v = ((const float4*)q)[i];
        ((uint4*)qt)[i] = make_uint4(f2tf(v.x), f2tf(v.y), f2tf(v.z), f2tf(v.w));
        float4 w = ((const float4*)k)[i];
        ((uint4*)kt)[i] = make_uint4(f2tf(w.x), f2tf(w.y), f2tf(w.z), f2tf(w.w));
    }
}

// ---------------------------------------------------------------------------
// Kernel 1: P = exp( (Qt.Kt^T / 32) * mask )  (unnormalized; k2 normalizes)
// CTA 128x128, BK=16, 128 threads = 4 warps (2Mx2N), warp tile 64x64.
// 3-stage cp.async ring (wait_group 1), register double-buffered fragments.
// ---------------------------------------------------------------------------
__global__ __launch_bounds__(128, 2)
void k1_qk_exp(const unsigned* __restrict__ Q, const unsigned* __restrict__ Kf,
               const float* __restrict__ mask, float* __restrict__ P)
{
    extern __shared__ unsigned sm[];
    unsigned* sA[3] = { sm, sm + 2560, sm + 2 * 2560 };
    unsigned* sB[3] = { sm + 3 * 2560, sm + 4 * 2560, sm + 5 * 2560 };

    const int b  = blockIdx.z;
    const int m0 = blockIdx.y * 128;
    const int n0 = blockIdx.x * 128;

    const unsigned* Qb = Q  + (size_t)b * LQ_ * HID_;
    const unsigned* Kb = Kf + (size_t)b * LK_ * HID_;

    const int tid  = threadIdx.x;
    const int wid  = tid >> 5;
    const int lane = tid & 31;
    const int qid  = lane >> 2;
    const int rid  = lane & 3;
    const int wm   = (wid & 1) * 64;
    const int wn   = (wid >> 1) * 64;

    const int lrow = tid >> 2;          // 0..31
    const int lkq  = (tid & 3) << 2;    // 0,4,8,12

    uint32_t sAa[3], sBa[3];
#pragma unroll
    for (int u = 0; u < 3; u++) {
        sAa[u] = (uint32_t)__cvta_generic_to_shared(sA[u]);
        sBa[u] = (uint32_t)__cvta_generic_to_shared(sB[u]);
    }

    float acc[4][8][4];
#pragma unroll
    for (int i = 0; i < 4; i++)
#pragma unroll
        for (int j = 0; j < 8; j++)
#pragma unroll
            for (int c = 0; c < 4; c++) acc[i][j][c] = 0.0f;

    auto fill = [&](int stage, int buf) {
        const int kk = stage * 16;
#pragma unroll
        for (int j = 0; j < 4; j++) {
            const int row = lrow + j * 32;
            cp_async16(sAa[buf] + (row * SK + lkq) * 4,
                       Qb + (size_t)(m0 + row) * HID_ + kk + lkq);
            cp_async16(sBa[buf] + (row * SK + lkq) * 4,
                       Kb + (size_t)(n0 + row) * HID_ + kk + lkq);
        }
    };

    fill(0, 0); CP_COMMIT();
    fill(1, 1); CP_COMMIT();

    const int NIT = HID_ / 16;
    int cur = 0;
    for (int it = 0; it < NIT; it++) {
        CP_WAIT1();
        __syncthreads();
        if (it + 2 < NIT) fill(it + 2, (it + 2) % 3);
        CP_COMMIT();                      // empty group on tail keeps counting valid
        const unsigned* cA = sA[cur];
        const unsigned* cB = sB[cur];
        cur = (cur + 1 == 3) ? 0 : cur + 1;

        // load BOTH ks-halves' fragments, then issue all 64 MMAs
        unsigned af[2][4][4];
        unsigned bf[2][8][2];
#pragma unroll
        for (int h = 0; h < 2; h++) {
            const int ks = h * 8;
#pragma unroll
            for (int mt = 0; mt < 4; mt++) {
                const int r = wm + mt * 16 + qid;
                af[h][mt][0] = cA[r * SK + ks + rid];
                af[h][mt][1] = cA[(r + 8) * SK + ks + rid];
                af[h][mt][2] = cA[r * SK + ks + 4 + rid];
                af[h][mt][3] = cA[(r + 8) * SK + ks + 4 + rid];
            }
#pragma unroll
            for (int nt = 0; nt < 8; nt++) {
                const int c = wn + nt * 8 + qid;
                bf[h][nt][0] = cB[c * SK + ks + rid];
                bf[h][nt][1] = cB[c * SK + ks + 4 + rid];
            }
        }
#pragma unroll
        for (int h = 0; h < 2; h++)
#pragma unroll
            for (int mt = 0; mt < 4; mt++)
#pragma unroll
                for (int nt = 0; nt < 8; nt++)
                    mma_tf32(acc[mt][nt], af[h][mt], bf[h][nt]);
        __syncthreads();
    }

    const float s = 0.03125f;
#pragma unroll
    for (int mt = 0; mt < 4; mt++) {
#pragma unroll
        for (int nt = 0; nt < 8; nt++) {
            const int r = m0 + wm + mt * 16 + qid;
            const int c = n0 + wn + nt * 8 + 2 * rid;
            const size_t i0 = ((size_t)b * LQ_ + r) * LK_ + c;
            const size_t i1 = ((size_t)b * LQ_ + r + 8) * LK_ + c;
            float2 ma = *(const float2*)(mask + i0);
            float2 mb = *(const float2*)(mask + i1);
            float2 o0, o1;
            o0.x = __expf(acc[mt][nt][0] * s * ma.x);
            o0.y = __expf(acc[mt][nt][1] * s * ma.y);
            o1.x = __expf(acc[mt][nt][2] * s * mb.x);
            o1.y = __expf(acc[mt][nt][3] * s * mb.y);
            *(float2*)(P + i0) = o0;
            *(float2*)(P + i1) = o1;
        }
    }
}

// ---------------------------------------------------------------------------
// Kernel 2: per-row normalization; also emit rna-rounded tf32 copy to g_At
// ---------------------------------------------------------------------------
__global__ __launch_bounds__(256)
void k2_norm(float* __restrict__ P, unsigned* __restrict__ Pt)
{
    __shared__ float red[256];
    float*    prow = P  + (size_t)blockIdx.x * LK_;
    unsigned* trow = Pt + (size_t)blockIdx.x * LK_;
    const int tid = threadIdx.x;

    float4 v0 = ((const float4*)prow)[tid];
    float4 v1 = ((const float4*)prow)[tid + 256];
    float s = v0.x + v0.y + v0.z + v0.w + v1.x + v1.y + v1.z + v1.w;
    red[tid] = s;
    __syncthreads();
#pragma unroll
    for (int off = 128; off > 0; off >>= 1) {
        if (tid < off) red[tid] += red[tid + off];
        __syncthreads();
    }
    const float inv = 1.0f / red[0];
    v0.x *= inv; v0.y *= inv; v0.z *= inv; v0.w *= inv;
    v1.x *= inv; v1.y *= inv; v1.z *= inv; v1.w *= inv;
    ((float4*)prow)[tid]       = v0;
    ((float4*)prow)[tid + 256] = v1;
    ((uint4*)trow)[tid] =
        make_uint4(f2tf(v0.x), f2tf(v0.y), f2tf(v0.z), f2tf(v0.w));
    ((uint4*)trow)[tid + 256] =
        make_uint4(f2tf(v1.x), f2tf(v1.y), f2tf(v1.z), f2tf(v1.w));
}

// ---------------------------------------------------------------------------
// Kernel 3: context = attn_t . Kt
// A [row][k] stride SK; B [k][n] stride SN. 3-stage ring + reg double-buffer.
// ---------------------------------------------------------------------------
__global__ __launch_bounds__(128, 2)
void k3_av(const unsigned* __restrict__ A, const unsigned* __restrict__ Kf,
           float* __restrict__ C)
{
    extern __shared__ unsigned sm[];
    unsigned* sA[3] = { sm, sm + 2560, sm + 2 * 2560 };
    unsigned* sB[3] = { sm + 3 * 2560,
                        sm + 3 * 2560 + 16 * SN,
                        sm + 3 * 2560 + 32 * SN };

    const int b  = blockIdx.z;
    const int m0 = blockIdx.y * 128;
    const int n0 = blockIdx.x * 128;

    const unsigned* Ab = A  + (size_t)b * LQ_ * LK_;
    const unsigned* Kb = Kf + (size_t)b * LK_ * HID_;

    const int tid  = threadIdx.x;
    const int wid  = tid >> 5;
    const int lane = tid & 31;
    const int qid  = lane >> 2;
    const int rid  = lane & 3;
    const int wm   = (wid & 1) * 64;
    const int wn   = (wid >> 1) * 64;

    const int lrow = tid >> 2;
    const int lkq  = (tid & 3) << 2;
    const int lkr  = tid >> 5;          // 0..3
    const int lnc  = (tid & 31) << 2;   // 0..124

    uint32_t sAa[3], sBa[3];
#pragma unroll
    for (int u = 0; u < 3; u++) {
        sAa[u] = (uint32_t)__cvta_generic_to_shared(sA[u]);
        sBa[u] = (uint32_t)__cvta_generic_to_shared(sB[u]);
    }

    float acc[4][8][4];
#pragma unroll
    for (int i = 0; i < 4; i++)
#pragma unroll
        for (int j = 0; j < 8; j++)
#pragma unroll
            for (int c = 0; c < 4; c++) acc[i][j][c] = 0.0f;

    auto fill = [&](int stage, int buf) {
        const int kk = stage * 16;
#pragma unroll
        for (int j = 0; j < 4; j++) {
            const int row = lrow + j * 32;
            cp_async16(sAa[buf] + (row * SK + lkq) * 4,
                       Ab + (size_t)(m0 + row) * LK_ + kk + lkq);
            const int kr = lkr + j * 4;
            cp_async16(sBa[buf] + (kr * SN + lnc) * 4,
                       Kb + (size_t)(kk + kr) * HID_ + n0 + lnc);
        }
    };

    fill(0, 0); CP_COMMIT();
    fill(1, 1); CP_COMMIT();

    const int NIT = LK_ / 16;
    int cur = 0;
    for (int it = 0; it < NIT; it++) {
        CP_WAIT1();
        __syncthreads();
        if (it + 2 < NIT) fill(it + 2, (it + 2) % 3);
        CP_COMMIT();
        const unsigned* cA = sA[cur];
        const unsigned* cB = sB[cur];
        cur = (cur + 1 == 3) ? 0 : cur + 1;

        unsigned af[2][4][4];
        unsigned bf[2][8][2];
#pragma unroll
        for (int h = 0; h < 2; h++) {
            const int ks = h * 8;
#pragma unroll
            for (int mt = 0; mt < 4; mt++) {
                const int r = wm + mt * 16 + qid;
                af[h][mt][0] = cA[r * SK + ks + rid];
                af[h][mt][1] = cA[(r + 8) * SK + ks + rid];
                af[h][mt][2] = cA[r * SK + ks + 4 + rid];
                af[h][mt][3] = cA[(r + 8) * SK + ks + 4 + rid];
            }
#pragma unroll
            for (int nt = 0; nt < 8; nt++) {
                const int c = wn + nt * 8 + qid;
                bf[h][nt][0] = cB[(ks + rid) * SN + c];
                bf[h][nt][1] = cB[(ks + 4 + rid) * SN + c];
            }
        }
#pragma unroll
        for (int h = 0; h < 2; h++)
#pragma unroll
            for (int mt = 0; mt < 4; mt++)
#pragma unroll
                for (int nt = 0; nt < 8; nt++)
                    mma_tf32(acc[mt][nt], af[h][mt], bf[h][nt]);
        __syncthreads();
    }

#pragma unroll
    for (int mt = 0; mt < 4; mt++) {
#pragma unroll
        for (int nt = 0; nt < 8; nt++) {
            const int r = m0 + wm + mt * 16 + qid;
            const int c = n0 + wn + nt * 8 + 2 * rid;
            const size_t i0 = ((size_t)b * LQ_ + r) * HID_ + c;
            const size_t i1 = ((size_t)b * LQ_ + r + 8) * HID_ + c;
            *(float2*)(C + i0) = make_float2(acc[mt][nt][0], acc[mt][nt][1]);
            *(float2*)(C + i1) = make_float2(acc[mt][nt][2], acc[mt][nt][3]);
        }
    }
}

// ---------------------------------------------------------------------------
extern "C" void kernel_launch(void* const* d_in, const int* in_sizes, int n_in,
                              void* d_out, int out_size)
{
    const float* Q    = (const float*)d_in[0];
    const float* Kf   = (const float*)d_in[1];
    const float* mask = (const float*)d_in[2];

    float* ctx  = (float*)d_out;                      // [B, LQ, HID]
    float* attn = ctx + (size_t)B_ * LQ_ * HID_;      // [B, LQ, LK]

    void *qt = 0, *kt = 0, *at = 0;
    cudaGetSymbolAddress(&qt, g_Qt);
    cudaGetSymbolAddress(&kt, g_Kt);
    cudaGetSymbolAddress(&at, g_At);

    const int smem1 = 6 * 2560 * 4;                        // 61440 B
    const int smem3 = (3 * 2560 + 3 * 16 * SN) * 4;        // 56832 B

    static bool attr_set = false;
    if (!attr_set) {
        cudaFuncSetAttribute(k1_qk_exp, cudaFuncAttributeMaxDynamicSharedMemorySize, smem1);
        cudaFuncSetAttribute(k3_av,     cudaFuncAttributeMaxDynamicSharedMemorySize, smem3);
        attr_set = true;
    }

    const int n4 = (B_ * LQ_ * HID_) / 4;
    k0_round<<<(n4 + 255) / 256, 256>>>(Q, Kf, (unsigned*)qt, (unsigned*)kt, n4);

    dim3 g1(LK_ / 128, LQ_ / 128, B_);
    k1_qk_exp<<<g1, 128, smem1>>>((const unsigned*)qt, (const unsigned*)kt, mask, attn);

    k2_norm<<<B_ * LQ_, 256>>>(attn, (unsigned*)at);

    dim3 g3(HID_ / 128, LQ_ / 128, B_);
    k3_av<<<g3, 128, smem3>>>((const unsigned*)at, (const unsigned*)kt, ctx);
}